// round 13
// baseline (speedup 1.0000x reference)
#include <cuda_runtime.h>
#include <cuda_bf16.h>
#include <math.h>
#include <stdint.h>

// Problem constants
#define N 8192
#define D 128
#define MARGIN 0.3f
#define TILE 128
#define PITCHB 272           // bytes per smem tile row (128 bf16 = 256B + 16B pad)

// Scratch (device globals -- allocation-free per harness rules)
__device__ float        g_sq[N];
__device__ unsigned int g_ap[N];     // float bits of hard-positive max
__device__ unsigned int g_an[N];     // float bits of hard-negative min
__device__ uint4        g_xb4[N * D * 2 / 16];   // bf16-rounded X, 16B chunks

// Dynamic smem layout (bytes)
#define SM_A     0
#define SM_B     (128 * PITCHB)                  // 34816
#define SM_META  (2 * 128 * PITCHB)              // 69632
#define SM_SQB   (SM_META + 0)                   // float[128]
#define SM_TGB   (SM_META + 512)                 // int[128]
#define SM_SAP   (SM_META + 1024)                // uint[128]
#define SM_SAN   (SM_META + 1536)                // uint[128]
#define SM_TOTAL (SM_META + 2048)                // 71680
// Epilogue stage reuses [0, SM_META): 8 warps x (32 rows x 68 floats) = 8x8704

__device__ __forceinline__ uint32_t smem_u32(const void* p) {
    uint32_t a;
    asm("{ .reg .u64 t; cvta.to.shared.u64 t, %1; cvt.u32.u64 %0, t; }"
        : "=r"(a) : "l"(p));
    return a;
}

__device__ __forceinline__ void cp_async16(uint32_t dst, const void* src) {
    asm volatile("cp.async.cg.shared.global [%0], [%1], 16;"
                 :: "r"(dst), "l"(src) : "memory");
}

// Bulk async store: smem -> gmem, 16B-aligned addresses, size % 16 == 0.
__device__ __forceinline__ void bulk_store(void* gdst, uint32_t ssrc, uint32_t bytes) {
    asm volatile("cp.async.bulk.global.shared::cta.bulk_group [%0], [%1], %2;"
                 :: "l"(gdst), "r"(ssrc), "r"(bytes) : "memory");
}

__device__ __forceinline__ void ldmatrix_x4(uint32_t* r, uint32_t addr) {
    asm volatile("ldmatrix.sync.aligned.m8n8.x4.shared.b16 {%0,%1,%2,%3}, [%4];"
                 : "=r"(r[0]), "=r"(r[1]), "=r"(r[2]), "=r"(r[3]) : "r"(addr));
}

__device__ __forceinline__ void mma16816(float* c, const uint32_t* a,
                                         uint32_t b0, uint32_t b1) {
    asm volatile(
        "mma.sync.aligned.m16n8k16.row.col.f32.bf16.bf16.f32 "
        "{%0,%1,%2,%3}, {%4,%5,%6,%7}, {%8,%9}, {%0,%1,%2,%3};"
        : "+f"(c[0]), "+f"(c[1]), "+f"(c[2]), "+f"(c[3])
        : "r"(a[0]), "r"(a[1]), "r"(a[2]), "r"(a[3]), "r"(b0), "r"(b1));
}

// ---------------------------------------------------------------------------
// Kernel 1: bf16-round X into g_xb4, row squared norms of the ROUNDED values
// (consistent quadratic form), init ap/an. One warp per row.
// ---------------------------------------------------------------------------
__global__ void prep_kernel(const float* __restrict__ x) {
    int row  = (blockIdx.x * blockDim.x + threadIdx.x) >> 5;
    int lane = threadIdx.x & 31;
    if (row >= N) return;
    const float4* xr = reinterpret_cast<const float4*>(x + (size_t)row * D);
    float4 v = xr[lane];
    union { __nv_bfloat162 h[2]; uint2 u; } ub;
    ub.h[0] = __floats2bfloat162_rn(v.x, v.y);
    ub.h[1] = __floats2bfloat162_rn(v.z, v.w);
    reinterpret_cast<uint2*>(g_xb4)[row * 32 + lane] = ub.u;
    float a0 = __bfloat162float(__float2bfloat16_rn(v.x));
    float a1 = __bfloat162float(__float2bfloat16_rn(v.y));
    float a2 = __bfloat162float(__float2bfloat16_rn(v.z));
    float a3 = __bfloat162float(__float2bfloat16_rn(v.w));
    float s = a0 * a0 + a1 * a1 + a2 * a2 + a3 * a3;
    #pragma unroll
    for (int o = 16; o > 0; o >>= 1) s += __shfl_xor_sync(0xffffffffu, s, o);
    if (lane == 0) {
        g_sq[row] = s;
        g_ap[row] = 0u;
        g_an[row] = 0x7f800000u;
    }
}

// ---------------------------------------------------------------------------
// Kernel 2: 128x128 distance tiles via mma.sync bf16 HMMA, async bulk store.
// ---------------------------------------------------------------------------
__global__ __launch_bounds__(256, 2)
void dist_kernel(const int* __restrict__ tgt, float* __restrict__ out) {
    extern __shared__ char smem[];
    const uint32_t sbase = smem_u32(smem);
    const int t    = threadIdx.x;
    const int lane = t & 31;
    const int wid  = t >> 5;
    const int iBase = blockIdx.y * TILE;
    const int jBase = blockIdx.x * TILE;

    float*    sqB = (float*)(smem + SM_SQB);
    int*      tgB = (int*)(smem + SM_TGB);
    unsigned* sAp = (unsigned*)(smem + SM_SAP);
    unsigned* sAn = (unsigned*)(smem + SM_SAN);

    if (t < 128) {
        sqB[t] = g_sq[jBase + t];
        tgB[t] = tgt[jBase + t];
        sAp[t] = 0u;
        sAn[t] = 0x7f800000u;
    }

    // Tile fill via cp.async: 16B chunks of pre-rounded bf16 rows.
    {
        #pragma unroll
        for (int it = 0; it < 8; it++) {
            int idx = t + it * 256;           // 0..2047
            int row = idx >> 4, l = idx & 15;
            cp_async16(sbase + SM_A + row * PITCHB + l * 16,
                       &g_xb4[(size_t)(iBase + row) * 16 + l]);
            cp_async16(sbase + SM_B + row * PITCHB + l * 16,
                       &g_xb4[(size_t)(jBase + row) * 16 + l]);
        }
        asm volatile("cp.async.commit_group;" ::: "memory");
        asm volatile("cp.async.wait_group 0;" ::: "memory");
    }
    __syncthreads();

    const int rw0 = (wid & 3) * 32;     // warp sub-tile row base (tile-local)
    const int cw0 = (wid >> 2) * 64;    // warp sub-tile col base (tile-local)

    float acc[2][8][4];
    #pragma unroll
    for (int mt = 0; mt < 2; mt++)
        #pragma unroll
        for (int nt = 0; nt < 8; nt++)
            #pragma unroll
            for (int e = 0; e < 4; e++) acc[mt][nt][e] = 0.f;

    const uint32_t aB  = sbase + SM_A;
    const uint32_t bB  = sbase + SM_B;
    const int lrow = lane & 15;
    const int koff = (lane >> 4) * 8;

    #pragma unroll
    for (int ks = 0; ks < 8; ks++) {
        const int k0 = ks * 16;
        uint32_t af[2][4];
        #pragma unroll
        for (int mt = 0; mt < 2; mt++)
            ldmatrix_x4(af[mt],
                aB + (uint32_t)(rw0 + 16 * mt + lrow) * PITCHB + (k0 + koff) * 2);
        uint32_t bf[4][4];
        #pragma unroll
        for (int ng = 0; ng < 4; ng++)
            ldmatrix_x4(bf[ng],
                bB + (uint32_t)(cw0 + 16 * ng + lrow) * PITCHB + (k0 + koff) * 2);
        #pragma unroll
        for (int mt = 0; mt < 2; mt++)
            #pragma unroll
            for (int ng = 0; ng < 4; ng++) {
                mma16816(acc[mt][2 * ng + 0], af[mt], bf[ng][0], bf[ng][2]);
                mma16816(acc[mt][2 * ng + 1], af[mt], bf[ng][1], bf[ng][3]);
            }
    }
    __syncthreads();   // ldmatrix reads done -> A/B smem reusable as stage

    // Epilogue. Stage layout: stage[r][c] holds dist for global col (c-1),
    // pitch 68 floats, so 16B-aligned reads at c=4k map to global cols 4k-1
    // (=3 mod 4), exactly where the d_out+1 shift restores 16B alignment.
    float* stage = (float*)(smem + (size_t)wid * 8704);
    const int qr = lane >> 2;            // 0..7
    const int qc = 2 * (lane & 3);       // 0,2,4,6
    const float INF = __int_as_float(0x7f800000);

    #pragma unroll
    for (int mt = 0; mt < 2; mt++) {
        const int rl_lo = rw0 + 16 * mt + qr;
        const int rl_hi = rl_lo + 8;
        const int rg_lo = iBase + rl_lo;
        const int rg_hi = iBase + rl_hi;
        const float sq_lo = g_sq[rg_lo], sq_hi = g_sq[rg_hi];
        const int   tt_lo = tgt[rg_lo],  tt_hi = tgt[rg_hi];
        float ap_lo = 0.f, an_lo = INF, ap_hi = 0.f, an_hi = INF;

        #pragma unroll
        for (int nt = 0; nt < 8; nt++) {
            const int cl0 = cw0 + 8 * nt + qc;
            const float sc0 = sqB[cl0], sc1 = sqB[cl0 + 1];
            const int   tc0 = tgB[cl0], tc1 = tgB[cl0 + 1];
            const int   cg0 = jBase + cl0;

            float s00 = sq_lo + sc0 - 2.f * acc[mt][nt][0];
            float s01 = sq_lo + sc1 - 2.f * acc[mt][nt][1];
            float s10 = sq_hi + sc0 - 2.f * acc[mt][nt][2];
            float s11 = sq_hi + sc1 - 2.f * acc[mt][nt][3];
            float d00 = (s00 > 0.f) ? sqrtf(s00) : 0.f;
            float d01 = (s01 > 0.f) ? sqrtf(s01) : 0.f;
            float d10 = (s10 > 0.f) ? sqrtf(s10) : 0.f;
            float d11 = (s11 > 0.f) ? sqrtf(s11) : 0.f;
            if (rg_lo == cg0)     d00 = 0.f;      // exact diagonal, like ref
            if (rg_lo == cg0 + 1) d01 = 0.f;
            if (rg_hi == cg0)     d10 = 0.f;
            if (rg_hi == cg0 + 1) d11 = 0.f;

            if (tt_lo == tc0) ap_lo = fmaxf(ap_lo, d00); else an_lo = fminf(an_lo, d00);
            if (tt_lo == tc1) ap_lo = fmaxf(ap_lo, d01); else an_lo = fminf(an_lo, d01);
            if (tt_hi == tc0) ap_hi = fmaxf(ap_hi, d10); else an_hi = fminf(an_hi, d10);
            if (tt_hi == tc1) ap_hi = fmaxf(ap_hi, d11); else an_hi = fminf(an_hi, d11);

            const int sr = 16 * mt + qr;          // warp-slab-local row
            const int sc = 8 * nt + qc + 1;       // shifted column (c = jloc+1)
            stage[sr * 68 + sc]           = d00;
            stage[sr * 68 + sc + 1]       = d01;
            stage[(sr + 8) * 68 + sc]     = d10;
            stage[(sr + 8) * 68 + sc + 1] = d11;
        }

        // quad reduce (lanes 4r..4r+3 share the same rows)
        #pragma unroll
        for (int o = 1; o <= 2; o <<= 1) {
            ap_lo = fmaxf(ap_lo, __shfl_xor_sync(0xffffffffu, ap_lo, o));
            an_lo = fminf(an_lo, __shfl_xor_sync(0xffffffffu, an_lo, o));
            ap_hi = fmaxf(ap_hi, __shfl_xor_sync(0xffffffffu, ap_hi, o));
            an_hi = fminf(an_hi, __shfl_xor_sync(0xffffffffu, an_hi, o));
        }
        if ((lane & 3) == 0) {
            atomicMax(&sAp[rl_lo], __float_as_uint(ap_lo));
            atomicMin(&sAn[rl_lo], __float_as_uint(an_lo));
            atomicMax(&sAp[rl_hi], __float_as_uint(ap_hi));
            atomicMin(&sAn[rl_hi], __float_as_uint(an_hi));
        }
    }
    __syncwarp();
    asm volatile("fence.proxy.async.shared::cta;" ::: "memory");  // STS -> bulk

    // Async bulk stores: one 240B DMA per row (cols 3..62 of the slab),
    // plus lane-parallel scalar edges for cols {0,1,2,63}.
    {
        const size_t rowBase = (size_t)(iBase + rw0) * N + jBase + cw0;
        // 32 rows, one per lane: src 16B-aligned, dst 16B-aligned, 240B.
        bulk_store(out + rowBase + (size_t)lane * N + 3,
                   sbase + wid * 8704u + (uint32_t)lane * 272u + 16u, 240u);
        asm volatile("cp.async.bulk.commit_group;" ::: "memory");

        const int e  = lane & 3;
        const int jl = (e == 3) ? 63 : e;
        #pragma unroll
        for (int it = 0; it < 4; it++) {
            int row = (it * 32 + lane) >> 2;
            out[rowBase + (size_t)row * N + jl] = stage[row * 68 + jl + 1];
        }
    }

    __syncthreads();
    if (t < 128) {
        atomicMax(&g_ap[iBase + t], sAp[t]);
        atomicMin(&g_an[iBase + t], sAn[t]);
    }
    // Drain bulk DMAs before CTA exit (smem is recycled by the next CTA).
    asm volatile("cp.async.bulk.wait_group 0;" ::: "memory");
}

// ---------------------------------------------------------------------------
// Kernel 3: loss = mean(relu(ap - an + margin)). Single block.
// ---------------------------------------------------------------------------
__global__ void loss_kernel(float* __restrict__ out) {
    __shared__ float red[32];
    float s = 0.f;
    for (int i = threadIdx.x; i < N; i += blockDim.x) {
        float ap = __uint_as_float(g_ap[i]);
        float an = __uint_as_float(g_an[i]);
        float v  = ap - an + MARGIN;
        s += (v > 0.f) ? v : 0.f;
    }
    #pragma unroll
    for (int o = 16; o > 0; o >>= 1) s += __shfl_xor_sync(0xffffffffu, s, o);
    int lane = threadIdx.x & 31, wid = threadIdx.x >> 5;
    if (lane == 0) red[wid] = s;
    __syncthreads();
    if (wid == 0) {
        s = (lane < (blockDim.x >> 5)) ? red[lane] : 0.f;
        #pragma unroll
        for (int o = 16; o > 0; o >>= 1) s += __shfl_xor_sync(0xffffffffu, s, o);
        if (lane == 0) out[0] = s / (float)N;
    }
}

// ---------------------------------------------------------------------------
extern "C" void kernel_launch(void* const* d_in, const int* in_sizes, int n_in,
                              void* d_out, int out_size) {
    const float* x   = (const float*)d_in[0];
    const int*   tgt = (const int*)d_in[1];
    float* out = (float*)d_out;           // out[0] = loss, out[1..] = dist

    cudaFuncSetAttribute(dist_kernel,
                         cudaFuncAttributeMaxDynamicSharedMemorySize, SM_TOTAL);

    prep_kernel<<<N / 8, 256>>>(x);

    dim3 grid(N / TILE, N / TILE);
    dist_kernel<<<grid, 256, SM_TOTAL>>>(tgt, out + 1);

    loss_kernel<<<1, 1024>>>(out);
}

// round 14
// speedup vs baseline: 1.0709x; 1.0709x over previous
#include <cuda_runtime.h>
#include <cuda_bf16.h>
#include <math.h>
#include <stdint.h>

// Problem constants
#define N 8192
#define D 128
#define MARGIN 0.3f
#define TILE 128
#define JT 4                 // j-tiles per CTA (strip sweep)
#define PITCHB 272           // bytes per smem tile row (128 bf16 = 256B + 16B pad)

// Scratch (device globals -- allocation-free per harness rules)
__device__ float        g_sq[N];
__device__ unsigned int g_ap[N];     // float bits of hard-positive max
__device__ unsigned int g_an[N];     // float bits of hard-negative min
__device__ uint4        g_xb4[N * D * 2 / 16];   // bf16-rounded X, 16B chunks

// Dynamic smem layout (bytes)
#define SM_A     0                               // 34816
#define SM_B     34816                           // 34816
#define SM_STG   69632                           // 8 warps x 16 rows x 68 f = 34816
#define SM_MQ    104448                          // sq2[2][128] f
#define SM_TG    (SM_MQ + 1024)                  // tg2[2][128] i
#define SM_SAP   (SM_MQ + 2048)                  // uint[128]
#define SM_SAN   (SM_MQ + 2560)                  // uint[128]
#define SM_TOTAL (SM_MQ + 3072)                  // 107520 (2 CTAs/SM fit in 228KB)

__device__ __forceinline__ uint32_t smem_u32(const void* p) {
    uint32_t a;
    asm("{ .reg .u64 t; cvta.to.shared.u64 t, %1; cvt.u32.u64 %0, t; }"
        : "=r"(a) : "l"(p));
    return a;
}

__device__ __forceinline__ void cp_async16(uint32_t dst, const void* src) {
    asm volatile("cp.async.cg.shared.global [%0], [%1], 16;"
                 :: "r"(dst), "l"(src) : "memory");
}

__device__ __forceinline__ void bulk_store(void* gdst, uint32_t ssrc, uint32_t bytes) {
    asm volatile("cp.async.bulk.global.shared::cta.bulk_group [%0], [%1], %2;"
                 :: "l"(gdst), "r"(ssrc), "r"(bytes) : "memory");
}

__device__ __forceinline__ void ldmatrix_x4(uint32_t* r, uint32_t addr) {
    asm volatile("ldmatrix.sync.aligned.m8n8.x4.shared.b16 {%0,%1,%2,%3}, [%4];"
                 : "=r"(r[0]), "=r"(r[1]), "=r"(r[2]), "=r"(r[3]) : "r"(addr));
}

__device__ __forceinline__ void mma16816(float* c, const uint32_t* a,
                                         uint32_t b0, uint32_t b1) {
    asm volatile(
        "mma.sync.aligned.m16n8k16.row.col.f32.bf16.bf16.f32 "
        "{%0,%1,%2,%3}, {%4,%5,%6,%7}, {%8,%9}, {%0,%1,%2,%3};"
        : "+f"(c[0]), "+f"(c[1]), "+f"(c[2]), "+f"(c[3])
        : "r"(a[0]), "r"(a[1]), "r"(a[2]), "r"(a[3]), "r"(b0), "r"(b1));
}

// ---------------------------------------------------------------------------
// Kernel 1: bf16-round X into g_xb4 + row sq-norms of ROUNDED values + init.
// ---------------------------------------------------------------------------
__global__ void prep_kernel(const float* __restrict__ x) {
    int row  = (blockIdx.x * blockDim.x + threadIdx.x) >> 5;
    int lane = threadIdx.x & 31;
    if (row >= N) return;
    const float4* xr = reinterpret_cast<const float4*>(x + (size_t)row * D);
    float4 v = xr[lane];
    union { __nv_bfloat162 h[2]; uint2 u; } ub;
    ub.h[0] = __floats2bfloat162_rn(v.x, v.y);
    ub.h[1] = __floats2bfloat162_rn(v.z, v.w);
    reinterpret_cast<uint2*>(g_xb4)[row * 32 + lane] = ub.u;
    float a0 = __bfloat162float(__float2bfloat16_rn(v.x));
    float a1 = __bfloat162float(__float2bfloat16_rn(v.y));
    float a2 = __bfloat162float(__float2bfloat16_rn(v.z));
    float a3 = __bfloat162float(__float2bfloat16_rn(v.w));
    float s = a0 * a0 + a1 * a1 + a2 * a2 + a3 * a3;
    #pragma unroll
    for (int o = 16; o > 0; o >>= 1) s += __shfl_xor_sync(0xffffffffu, s, o);
    if (lane == 0) {
        g_sq[row] = s;
        g_ap[row] = 0u;
        g_an[row] = 0x7f800000u;
    }
}

// ---------------------------------------------------------------------------
// Kernel 2: strip kernel. A tile resident; sweep JT j-tiles with B prefetch
// overlapping the epilogue. grid = (N/(TILE*JT), N/TILE).
// ---------------------------------------------------------------------------
__global__ __launch_bounds__(256, 2)
void dist_kernel(const int* __restrict__ tgt, float* __restrict__ out) {
    extern __shared__ char smem[];
    const uint32_t sbase = smem_u32(smem);
    const int t    = threadIdx.x;
    const int lane = t & 31;
    const int wid  = t >> 5;
    const int iBase  = blockIdx.y * TILE;
    const int jBase0 = blockIdx.x * (TILE * JT);

    float*    sq2 = (float*)(smem + SM_MQ);
    int*      tg2 = (int*)(smem + SM_TG);
    unsigned* sAp = (unsigned*)(smem + SM_SAP);
    unsigned* sAn = (unsigned*)(smem + SM_SAN);

    // Prologue: meta for q=0, ap/an init, A fill + B0 fill.
    if (t < 128) {
        sq2[t] = g_sq[jBase0 + t];
        tg2[t] = tgt[jBase0 + t];
        sAp[t] = 0u;
        sAn[t] = 0x7f800000u;
    }
    #pragma unroll
    for (int it = 0; it < 8; it++) {
        int idx = t + it * 256;               // 0..2047
        int row = idx >> 4, l = idx & 15;
        cp_async16(sbase + SM_A + row * PITCHB + l * 16,
                   &g_xb4[(size_t)(iBase + row) * 16 + l]);
        cp_async16(sbase + SM_B + row * PITCHB + l * 16,
                   &g_xb4[(size_t)(jBase0 + row) * 16 + l]);
    }
    asm volatile("cp.async.commit_group;" ::: "memory");
    asm volatile("cp.async.wait_group 0;" ::: "memory");
    __syncthreads();

    const int rw0 = (wid & 3) * 32;     // warp rows (tile-local)
    const int cw0 = (wid >> 2) * 64;    // warp cols (tile-local)
    const uint32_t aB = sbase + SM_A;
    const uint32_t bB = sbase + SM_B;
    const int lrow = lane & 15;
    const int koff = (lane >> 4) * 8;
    const int qr = lane >> 2;           // 0..7
    const int qc = 2 * (lane & 3);      // 0,2,4,6
    const float INF = __int_as_float(0x7f800000);

    // Per-strip row metadata + running hard-pos/neg (persist across j-tiles)
    float sqR[2][2]; int ttR[2][2];
    float apR[2][2], anR[2][2];
    #pragma unroll
    for (int mt = 0; mt < 2; mt++) {
        int rg = iBase + rw0 + 16 * mt + qr;
        sqR[mt][0] = g_sq[rg];     sqR[mt][1] = g_sq[rg + 8];
        ttR[mt][0] = tgt[rg];      ttR[mt][1] = tgt[rg + 8];
        apR[mt][0] = apR[mt][1] = 0.f;
        anR[mt][0] = anR[mt][1] = INF;
    }

    float* stage = (float*)(smem + SM_STG + wid * 4352);   // 16 rows x 68 f

    #pragma unroll 1
    for (int q = 0; q < JT; q++) {
        const int jBase = jBase0 + q * TILE;

        // ---- mainloop on B_q ----
        float acc[2][8][4];
        #pragma unroll
        for (int mt = 0; mt < 2; mt++)
            #pragma unroll
            for (int nt = 0; nt < 8; nt++)
                #pragma unroll
                for (int e = 0; e < 4; e++) acc[mt][nt][e] = 0.f;

        #pragma unroll
        for (int ks = 0; ks < 8; ks++) {
            const int k0 = ks * 16;
            uint32_t af[2][4];
            #pragma unroll
            for (int mt = 0; mt < 2; mt++)
                ldmatrix_x4(af[mt],
                    aB + (uint32_t)(rw0 + 16 * mt + lrow) * PITCHB + (k0 + koff) * 2);
            uint32_t bf[4][4];
            #pragma unroll
            for (int ng = 0; ng < 4; ng++)
                ldmatrix_x4(bf[ng],
                    bB + (uint32_t)(cw0 + 16 * ng + lrow) * PITCHB + (k0 + koff) * 2);
            #pragma unroll
            for (int mt = 0; mt < 2; mt++)
                #pragma unroll
                for (int ng = 0; ng < 4; ng++) {
                    mma16816(acc[mt][2 * ng + 0], af[mt], bf[ng][0], bf[ng][2]);
                    mma16816(acc[mt][2 * ng + 1], af[mt], bf[ng][1], bf[ng][3]);
                }
        }
        __syncthreads();                 // all warps done reading B_q

        // ---- prefetch B_{q+1} + its meta; overlaps the epilogue below ----
        if (q < JT - 1) {
            #pragma unroll
            for (int it = 0; it < 8; it++) {
                int idx = t + it * 256;
                int row = idx >> 4, l = idx & 15;
                cp_async16(sbase + SM_B + row * PITCHB + l * 16,
                           &g_xb4[(size_t)(jBase + TILE + row) * 16 + l]);
            }
            asm volatile("cp.async.commit_group;" ::: "memory");
            if (t < 128) {
                int nb = ((q + 1) & 1) * 128;
                sq2[nb + t] = g_sq[jBase + TILE + t];
                tg2[nb + t] = tgt[jBase + TILE + t];
            }
        }

        // ---- epilogue for tile q ----
        const float* sqB = sq2 + (q & 1) * 128;
        const int*   tgB = tg2 + (q & 1) * 128;

        #pragma unroll
        for (int mt = 0; mt < 2; mt++) {
            // stage free? wait for previous bulk reads, warp-wide
            if (lane < 16)
                asm volatile("cp.async.bulk.wait_group 0;" ::: "memory");
            __syncwarp();

            const int rg_lo = iBase + rw0 + 16 * mt + qr;
            const int rg_hi = rg_lo + 8;
            const float sq_lo = sqR[mt][0], sq_hi = sqR[mt][1];
            const int   tt_lo = ttR[mt][0], tt_hi = ttR[mt][1];

            #pragma unroll
            for (int nt = 0; nt < 8; nt++) {
                const int cl0 = cw0 + 8 * nt + qc;
                const float sc0 = sqB[cl0], sc1 = sqB[cl0 + 1];
                const int   tc0 = tgB[cl0], tc1 = tgB[cl0 + 1];
                const int   cg0 = jBase + cl0;

                float s00 = sq_lo + sc0 - 2.f * acc[mt][nt][0];
                float s01 = sq_lo + sc1 - 2.f * acc[mt][nt][1];
                float s10 = sq_hi + sc0 - 2.f * acc[mt][nt][2];
                float s11 = sq_hi + sc1 - 2.f * acc[mt][nt][3];
                float d00 = (s00 > 0.f) ? sqrtf(s00) : 0.f;
                float d01 = (s01 > 0.f) ? sqrtf(s01) : 0.f;
                float d10 = (s10 > 0.f) ? sqrtf(s10) : 0.f;
                float d11 = (s11 > 0.f) ? sqrtf(s11) : 0.f;
                if (rg_lo == cg0)     d00 = 0.f;   // exact diagonal, like ref
                if (rg_lo == cg0 + 1) d01 = 0.f;
                if (rg_hi == cg0)     d10 = 0.f;
                if (rg_hi == cg0 + 1) d11 = 0.f;

                if (tt_lo == tc0) apR[mt][0] = fmaxf(apR[mt][0], d00);
                else              anR[mt][0] = fminf(anR[mt][0], d00);
                if (tt_lo == tc1) apR[mt][0] = fmaxf(apR[mt][0], d01);
                else              anR[mt][0] = fminf(anR[mt][0], d01);
                if (tt_hi == tc0) apR[mt][1] = fmaxf(apR[mt][1], d10);
                else              anR[mt][1] = fminf(anR[mt][1], d10);
                if (tt_hi == tc1) apR[mt][1] = fmaxf(apR[mt][1], d11);
                else              anR[mt][1] = fminf(anR[mt][1], d11);

                const int sc = 8 * nt + qc + 1;    // +1 shift for alignment
                stage[qr * 68 + sc]           = d00;
                stage[qr * 68 + sc + 1]       = d01;
                stage[(qr + 8) * 68 + sc]     = d10;
                stage[(qr + 8) * 68 + sc + 1] = d11;
            }
            __syncwarp();
            asm volatile("fence.proxy.async.shared::cta;" ::: "memory");

            const size_t rowBase = (size_t)(iBase + rw0 + 16 * mt) * N + jBase + cw0;
            if (lane < 16) {
                bulk_store(out + rowBase + (size_t)lane * N + 3,
                           sbase + SM_STG + wid * 4352u + (uint32_t)lane * 272u + 16u,
                           240u);
                asm volatile("cp.async.bulk.commit_group;" ::: "memory");
            }
            // edge cols {0,1,2,63}: 16 rows x 4 = 64 scalars, 2 per lane
            #pragma unroll
            for (int it = 0; it < 2; it++) {
                int idx = it * 32 + lane;
                int row = idx >> 2, e = idx & 3;
                int jl  = (e == 3) ? 63 : e;
                out[rowBase + (size_t)row * N + jl] = stage[row * 68 + jl + 1];
            }
        }

        // B_{q+1} + meta ready before next mainloop
        if (q < JT - 1) {
            asm volatile("cp.async.wait_group 0;" ::: "memory");
            __syncthreads();
        }
    }

    // ---- once-per-CTA hard-pos/neg reduction ----
    #pragma unroll
    for (int mt = 0; mt < 2; mt++) {
        #pragma unroll
        for (int h = 0; h < 2; h++) {
            float ap = apR[mt][h], an = anR[mt][h];
            #pragma unroll
            for (int o = 1; o <= 2; o <<= 1) {
                ap = fmaxf(ap, __shfl_xor_sync(0xffffffffu, ap, o));
                an = fminf(an, __shfl_xor_sync(0xffffffffu, an, o));
            }
            if ((lane & 3) == 0) {
                int rl = rw0 + 16 * mt + 8 * h + qr;
                atomicMax(&sAp[rl], __float_as_uint(ap));
                atomicMin(&sAn[rl], __float_as_uint(an));
            }
        }
    }
    // drain bulk DMAs before smem is recycled
    if (lane < 16)
        asm volatile("cp.async.bulk.wait_group 0;" ::: "memory");
    __syncthreads();
    if (t < 128) {
        atomicMax(&g_ap[iBase + t], sAp[t]);
        atomicMin(&g_an[iBase + t], sAn[t]);
    }
}

// ---------------------------------------------------------------------------
// Kernel 3: loss = mean(relu(ap - an + margin)). Single block.
// ---------------------------------------------------------------------------
__global__ void loss_kernel(float* __restrict__ out) {
    __shared__ float red[32];
    float s = 0.f;
    for (int i = threadIdx.x; i < N; i += blockDim.x) {
        float ap = __uint_as_float(g_ap[i]);
        float an = __uint_as_float(g_an[i]);
        float v  = ap - an + MARGIN;
        s += (v > 0.f) ? v : 0.f;
    }
    #pragma unroll
    for (int o = 16; o > 0; o >>= 1) s += __shfl_xor_sync(0xffffffffu, s, o);
    int lane = threadIdx.x & 31, wid = threadIdx.x >> 5;
    if (lane == 0) red[wid] = s;
    __syncthreads();
    if (wid == 0) {
        s = (lane < (blockDim.x >> 5)) ? red[lane] : 0.f;
        #pragma unroll
        for (int o = 16; o > 0; o >>= 1) s += __shfl_xor_sync(0xffffffffu, s, o);
        if (lane == 0) out[0] = s / (float)N;
    }
}

// ---------------------------------------------------------------------------
extern "C" void kernel_launch(void* const* d_in, const int* in_sizes, int n_in,
                              void* d_out, int out_size) {
    const float* x   = (const float*)d_in[0];
    const int*   tgt = (const int*)d_in[1];
    float* out = (float*)d_out;           // out[0] = loss, out[1..] = dist

    cudaFuncSetAttribute(dist_kernel,
                         cudaFuncAttributeMaxDynamicSharedMemorySize, SM_TOTAL);

    prep_kernel<<<N / 8, 256>>>(x);

    dim3 grid(N / (TILE * JT), N / TILE);
    dist_kernel<<<grid, 256, SM_TOTAL>>>(tgt, out + 1);

    loss_kernel<<<1, 1024>>>(out);
}

// round 15
// speedup vs baseline: 1.2134x; 1.1330x over previous
#include <cuda_runtime.h>
#include <cuda_bf16.h>
#include <math.h>
#include <stdint.h>

// Problem constants
#define N 8192
#define D 128
#define MARGIN 0.3f
#define TILE 128
#define NB (N / TILE)        // 64 tile-blocks per side
#define PITCHB 272           // bytes per smem tile row (128 bf16 = 256B + 16B pad)

// Scratch (device globals -- allocation-free per harness rules)
__device__ float        g_sq[N];
__device__ unsigned int g_ap[N];     // float bits of hard-positive max
__device__ unsigned int g_an[N];     // float bits of hard-negative min
__device__ uint4        g_xb4[N * D * 2 / 16];   // bf16-rounded X, 16B chunks

// Dynamic smem layout (bytes)
#define SM_A     0                               // 34816
#define SM_B     34816                           // 34816
#define SM_STG   69632                           // 8 warps x 16 rows x 68 f = 34816
#define SM_META  104448
#define SM_SQB   (SM_META + 0)                   // float[128] sq of block bj
#define SM_TGB   (SM_META + 512)                 // int[128]   tgt of block bj
#define SM_TGI   (SM_META + 1024)                // int[128]   tgt of block bi
#define SM_SAP   (SM_META + 1536)                // uint[128]  rows (block bi)
#define SM_SAN   (SM_META + 2048)
#define SM_SAPC  (SM_META + 2560)                // uint[128]  cols (block bj)
#define SM_SANC  (SM_META + 3072)
#define SM_TOTAL (SM_META + 3584)                // 108032 -> 2 CTAs/SM

__device__ __forceinline__ uint32_t smem_u32(const void* p) {
    uint32_t a;
    asm("{ .reg .u64 t; cvta.to.shared.u64 t, %1; cvt.u32.u64 %0, t; }"
        : "=r"(a) : "l"(p));
    return a;
}

__device__ __forceinline__ void cp_async16(uint32_t dst, const void* src) {
    asm volatile("cp.async.cg.shared.global [%0], [%1], 16;"
                 :: "r"(dst), "l"(src) : "memory");
}

__device__ __forceinline__ void bulk_store(void* gdst, uint32_t ssrc, uint32_t bytes) {
    asm volatile("cp.async.bulk.global.shared::cta.bulk_group [%0], [%1], %2;"
                 :: "l"(gdst), "r"(ssrc), "r"(bytes) : "memory");
}

__device__ __forceinline__ void ldmatrix_x4(uint32_t* r, uint32_t addr) {
    asm volatile("ldmatrix.sync.aligned.m8n8.x4.shared.b16 {%0,%1,%2,%3}, [%4];"
                 : "=r"(r[0]), "=r"(r[1]), "=r"(r[2]), "=r"(r[3]) : "r"(addr));
}

__device__ __forceinline__ void mma16816(float* c, const uint32_t* a,
                                         uint32_t b0, uint32_t b1) {
    asm volatile(
        "mma.sync.aligned.m16n8k16.row.col.f32.bf16.bf16.f32 "
        "{%0,%1,%2,%3}, {%4,%5,%6,%7}, {%8,%9}, {%0,%1,%2,%3};"
        : "+f"(c[0]), "+f"(c[1]), "+f"(c[2]), "+f"(c[3])
        : "r"(a[0]), "r"(a[1]), "r"(a[2]), "r"(a[3]), "r"(b0), "r"(b1));
}

// ---------------------------------------------------------------------------
// Kernel 1: bf16-round X into g_xb4 + row sq-norms of ROUNDED values + init.
// ---------------------------------------------------------------------------
__global__ void prep_kernel(const float* __restrict__ x) {
    int row  = (blockIdx.x * blockDim.x + threadIdx.x) >> 5;
    int lane = threadIdx.x & 31;
    if (row >= N) return;
    const float4* xr = reinterpret_cast<const float4*>(x + (size_t)row * D);
    float4 v = xr[lane];
    union { __nv_bfloat162 h[2]; uint2 u; } ub;
    ub.h[0] = __floats2bfloat162_rn(v.x, v.y);
    ub.h[1] = __floats2bfloat162_rn(v.z, v.w);
    reinterpret_cast<uint2*>(g_xb4)[row * 32 + lane] = ub.u;
    float a0 = __bfloat162float(__float2bfloat16_rn(v.x));
    float a1 = __bfloat162float(__float2bfloat16_rn(v.y));
    float a2 = __bfloat162float(__float2bfloat16_rn(v.z));
    float a3 = __bfloat162float(__float2bfloat16_rn(v.w));
    float s = a0 * a0 + a1 * a1 + a2 * a2 + a3 * a3;
    #pragma unroll
    for (int o = 16; o > 0; o >>= 1) s += __shfl_xor_sync(0xffffffffu, s, o);
    if (lane == 0) {
        g_sq[row] = s;
        g_ap[row] = 0u;
        g_an[row] = 0x7f800000u;
    }
}

// ---------------------------------------------------------------------------
// Kernel 2: upper-triangular 128x128 tiles only (2080 CTAs). Off-diagonal
// tiles are mirrored: normal orientation via stage+bulk, transposed via
// direct STG; col-wise hard-pos/neg recovered from the staged tile.
// ---------------------------------------------------------------------------
__global__ __launch_bounds__(256, 2)
void dist_kernel(const int* __restrict__ tgt, float* __restrict__ out) {
    extern __shared__ char smem[];
    const uint32_t sbase = smem_u32(smem);
    const int t    = threadIdx.x;
    const int lane = t & 31;
    const int wid  = t >> 5;

    // decode upper-triangle tile (bi <= bj)
    int rem = blockIdx.x, bi = 0;
    while (rem >= NB - bi) { rem -= NB - bi; bi++; }
    const int bj = bi + rem;
    const int iBase = bi * TILE;
    const int jBase = bj * TILE;
    const bool isDiag = (bi == bj);

    float*    sqB  = (float*)(smem + SM_SQB);
    int*      tgB  = (int*)(smem + SM_TGB);
    int*      tgI  = (int*)(smem + SM_TGI);
    unsigned* sAp  = (unsigned*)(smem + SM_SAP);
    unsigned* sAn  = (unsigned*)(smem + SM_SAN);
    unsigned* sApC = (unsigned*)(smem + SM_SAPC);
    unsigned* sAnC = (unsigned*)(smem + SM_SANC);

    if (t < 128) {
        sqB[t]  = g_sq[jBase + t];
        tgB[t]  = tgt[jBase + t];
        tgI[t]  = tgt[iBase + t];
        sAp[t]  = 0u;          sAn[t]  = 0x7f800000u;
        sApC[t] = 0u;          sAnC[t] = 0x7f800000u;
    }

    // Tile fill via cp.async (pre-rounded bf16 rows)
    #pragma unroll
    for (int it = 0; it < 8; it++) {
        int idx = t + it * 256;               // 0..2047
        int row = idx >> 4, l = idx & 15;
        cp_async16(sbase + SM_A + row * PITCHB + l * 16,
                   &g_xb4[(size_t)(iBase + row) * 16 + l]);
        cp_async16(sbase + SM_B + row * PITCHB + l * 16,
                   &g_xb4[(size_t)(jBase + row) * 16 + l]);
    }
    asm volatile("cp.async.commit_group;" ::: "memory");
    asm volatile("cp.async.wait_group 0;" ::: "memory");
    __syncthreads();

    const int rw0 = (wid & 3) * 32;     // warp rows (tile-local)
    const int cw0 = (wid >> 2) * 64;    // warp cols (tile-local)
    const uint32_t aB = sbase + SM_A;
    const uint32_t bB = sbase + SM_B;
    const int lrow = lane & 15;
    const int koff = (lane >> 4) * 8;
    const int qr = lane >> 2;           // 0..7
    const int qc = 2 * (lane & 3);      // 0,2,4,6
    const float INF = __int_as_float(0x7f800000);

    float acc[2][8][4];
    #pragma unroll
    for (int mt = 0; mt < 2; mt++)
        #pragma unroll
        for (int nt = 0; nt < 8; nt++)
            #pragma unroll
            for (int e = 0; e < 4; e++) acc[mt][nt][e] = 0.f;

    #pragma unroll
    for (int ks = 0; ks < 8; ks++) {
        const int k0 = ks * 16;
        uint32_t af[2][4];
        #pragma unroll
        for (int mt = 0; mt < 2; mt++)
            ldmatrix_x4(af[mt],
                aB + (uint32_t)(rw0 + 16 * mt + lrow) * PITCHB + (k0 + koff) * 2);
        uint32_t bf[4][4];
        #pragma unroll
        for (int ng = 0; ng < 4; ng++)
            ldmatrix_x4(bf[ng],
                bB + (uint32_t)(cw0 + 16 * ng + lrow) * PITCHB + (k0 + koff) * 2);
        #pragma unroll
        for (int mt = 0; mt < 2; mt++)
            #pragma unroll
            for (int ng = 0; ng < 4; ng++) {
                mma16816(acc[mt][2 * ng + 0], af[mt], bf[ng][0], bf[ng][2]);
                mma16816(acc[mt][2 * ng + 1], af[mt], bf[ng][1], bf[ng][3]);
            }
    }
    // (stage is a separate smem region; no barrier needed before epilogue)

    float* stage = (float*)(smem + SM_STG + wid * 4352);   // 16 rows x 68 f

    #pragma unroll
    for (int mt = 0; mt < 2; mt++) {
        // ensure previous phase's bulk DMA has drained before restaging
        if (mt > 0 && lane < 16)
            asm volatile("cp.async.bulk.wait_group 0;" ::: "memory");
        __syncwarp();

        const int rl_lo = rw0 + 16 * mt + qr;
        const int rl_hi = rl_lo + 8;
        const int rg_lo = iBase + rl_lo;
        const int rg_hi = iBase + rl_hi;
        const float sq_lo = g_sq[rg_lo], sq_hi = g_sq[rg_hi];
        const int   tt_lo = tgI[rl_lo],  tt_hi = tgI[rl_hi];
        float ap_lo = 0.f, an_lo = INF, ap_hi = 0.f, an_hi = INF;

        #pragma unroll
        for (int nt = 0; nt < 8; nt++) {
            const int cl0 = cw0 + 8 * nt + qc;
            const float sc0 = sqB[cl0], sc1 = sqB[cl0 + 1];
            const int   tc0 = tgB[cl0], tc1 = tgB[cl0 + 1];
            const int   cg0 = jBase + cl0;

            float s00 = sq_lo + sc0 - 2.f * acc[mt][nt][0];
            float s01 = sq_lo + sc1 - 2.f * acc[mt][nt][1];
            float s10 = sq_hi + sc0 - 2.f * acc[mt][nt][2];
            float s11 = sq_hi + sc1 - 2.f * acc[mt][nt][3];
            float d00 = (s00 > 0.f) ? sqrtf(s00) : 0.f;
            float d01 = (s01 > 0.f) ? sqrtf(s01) : 0.f;
            float d10 = (s10 > 0.f) ? sqrtf(s10) : 0.f;
            float d11 = (s11 > 0.f) ? sqrtf(s11) : 0.f;
            if (rg_lo == cg0)     d00 = 0.f;      // exact diagonal, like ref
            if (rg_lo == cg0 + 1) d01 = 0.f;
            if (rg_hi == cg0)     d10 = 0.f;
            if (rg_hi == cg0 + 1) d11 = 0.f;

            if (tt_lo == tc0) ap_lo = fmaxf(ap_lo, d00); else an_lo = fminf(an_lo, d00);
            if (tt_lo == tc1) ap_lo = fmaxf(ap_lo, d01); else an_lo = fminf(an_lo, d01);
            if (tt_hi == tc0) ap_hi = fmaxf(ap_hi, d10); else an_hi = fminf(an_hi, d10);
            if (tt_hi == tc1) ap_hi = fmaxf(ap_hi, d11); else an_hi = fminf(an_hi, d11);

            const int sc = 8 * nt + qc + 1;       // +1 shift for bulk alignment
            stage[qr * 68 + sc]           = d00;
            stage[qr * 68 + sc + 1]       = d01;
            stage[(qr + 8) * 68 + sc]     = d10;
            stage[(qr + 8) * 68 + sc + 1] = d11;

            // transposed (mirror) tile stores: out[jc*N + ir]
            if (!isDiag) {
                out[(size_t)cg0 * N + rg_lo]       = d00;
                out[(size_t)(cg0 + 1) * N + rg_lo] = d01;
                out[(size_t)cg0 * N + rg_hi]       = d10;
                out[(size_t)(cg0 + 1) * N + rg_hi] = d11;
            }
        }

        // row-wise (block bi) reduction: quad shuffle + shared atomics
        #pragma unroll
        for (int o = 1; o <= 2; o <<= 1) {
            ap_lo = fmaxf(ap_lo, __shfl_xor_sync(0xffffffffu, ap_lo, o));
            an_lo = fminf(an_lo, __shfl_xor_sync(0xffffffffu, an_lo, o));
            ap_hi = fmaxf(ap_hi, __shfl_xor_sync(0xffffffffu, ap_hi, o));
            an_hi = fminf(an_hi, __shfl_xor_sync(0xffffffffu, an_hi, o));
        }
        if ((lane & 3) == 0) {
            atomicMax(&sAp[rl_lo], __float_as_uint(ap_lo));
            atomicMin(&sAn[rl_lo], __float_as_uint(an_lo));
            atomicMax(&sAp[rl_hi], __float_as_uint(ap_hi));
            atomicMin(&sAn[rl_hi], __float_as_uint(an_hi));
        }
        __syncwarp();
        asm volatile("fence.proxy.async.shared::cta;" ::: "memory");

        // normal-orientation bulk store (cols 3..62 of slab) + scalar edges
        const size_t rowBase = (size_t)(iBase + rw0 + 16 * mt) * N + jBase + cw0;
        if (lane < 16) {
            bulk_store(out + rowBase + (size_t)lane * N + 3,
                       sbase + SM_STG + wid * 4352u + (uint32_t)lane * 272u + 16u,
                       240u);
            asm volatile("cp.async.bulk.commit_group;" ::: "memory");
        }
        #pragma unroll
        for (int it = 0; it < 2; it++) {
            int idx = it * 32 + lane;
            int row = idx >> 2, e = idx & 3;
            int jl  = (e == 3) ? 63 : e;
            out[rowBase + (size_t)row * N + jl] = stage[row * 68 + jl + 1];
        }

        // col-wise (block bj) reduction from the staged tile
        if (!isDiag) {
            const int c0 = cw0 + 2 * lane;            // 2 cols per lane
            const int tc0 = tgB[c0], tc1 = tgB[c0 + 1];
            float apc0 = 0.f, anc0 = INF, apc1 = 0.f, anc1 = INF;
            #pragma unroll
            for (int r = 0; r < 16; r++) {
                const int rt = tgI[rw0 + 16 * mt + r];
                float v0 = stage[r * 68 + 2 * lane + 1];
                float v1 = stage[r * 68 + 2 * lane + 2];
                if (rt == tc0) apc0 = fmaxf(apc0, v0); else anc0 = fminf(anc0, v0);
                if (rt == tc1) apc1 = fmaxf(apc1, v1); else anc1 = fminf(anc1, v1);
            }
            atomicMax(&sApC[c0],     __float_as_uint(apc0));
            atomicMin(&sAnC[c0],     __float_as_uint(anc0));
            atomicMax(&sApC[c0 + 1], __float_as_uint(apc1));
            atomicMin(&sAnC[c0 + 1], __float_as_uint(anc1));
        }
    }

    __syncthreads();
    if (t < 128) {
        atomicMax(&g_ap[iBase + t], sAp[t]);
        atomicMin(&g_an[iBase + t], sAn[t]);
        if (!isDiag) {
            atomicMax(&g_ap[jBase + t], sApC[t]);
            atomicMin(&g_an[jBase + t], sAnC[t]);
        }
    }
    // drain bulk DMAs before smem is recycled by the next CTA
    if (lane < 16)
        asm volatile("cp.async.bulk.wait_group 0;" ::: "memory");
}

// ---------------------------------------------------------------------------
// Kernel 3: loss = mean(relu(ap - an + margin)). Single block.
// ---------------------------------------------------------------------------
__global__ void loss_kernel(float* __restrict__ out) {
    __shared__ float red[32];
    float s = 0.f;
    for (int i = threadIdx.x; i < N; i += blockDim.x) {
        float ap = __uint_as_float(g_ap[i]);
        float an = __uint_as_float(g_an[i]);
        float v  = ap - an + MARGIN;
        s += (v > 0.f) ? v : 0.f;
    }
    #pragma unroll
    for (int o = 16; o > 0; o >>= 1) s += __shfl_xor_sync(0xffffffffu, s, o);
    int lane = threadIdx.x & 31, wid = threadIdx.x >> 5;
    if (lane == 0) red[wid] = s;
    __syncthreads();
    if (wid == 0) {
        s = (lane < (blockDim.x >> 5)) ? red[lane] : 0.f;
        #pragma unroll
        for (int o = 16; o > 0; o >>= 1) s += __shfl_xor_sync(0xffffffffu, s, o);
        if (lane == 0) out[0] = s / (float)N;
    }
}

// ---------------------------------------------------------------------------
extern "C" void kernel_launch(void* const* d_in, const int* in_sizes, int n_in,
                              void* d_out, int out_size) {
    const float* x   = (const float*)d_in[0];
    const int*   tgt = (const int*)d_in[1];
    float* out = (float*)d_out;           // out[0] = loss, out[1..] = dist

    cudaFuncSetAttribute(dist_kernel,
                         cudaFuncAttributeMaxDynamicSharedMemorySize, SM_TOTAL);

    prep_kernel<<<N / 8, 256>>>(x);

    dist_kernel<<<NB * (NB + 1) / 2, 256, SM_TOTAL>>>(tgt, out + 1);

    loss_kernel<<<1, 1024>>>(out);
}

// round 16
// speedup vs baseline: 1.4424x; 1.1887x over previous
#include <cuda_runtime.h>
#include <cuda_bf16.h>
#include <math.h>
#include <stdint.h>

// Problem constants
#define N 8192
#define D 128
#define MARGIN 0.3f
#define TILE 128
#define NB (N / TILE)        // 64 tile-blocks per side
#define PITCHB 272           // bytes per smem tile row (128 bf16 = 256B + 16B pad)
#define TPITCH 132           // floats per stage_T row (128 + shift + pad)

// Scratch (device globals -- allocation-free per harness rules)
__device__ float        g_sq[N];
__device__ unsigned int g_ap[N];     // float bits of hard-positive max
__device__ unsigned int g_an[N];     // float bits of hard-negative min
__device__ uint4        g_xb4[N * D * 2 / 16];   // bf16-rounded X, 16B chunks

// Dynamic smem layout (bytes)
#define SM_A     0                               // 34816  (reused as stage_T)
#define SM_B     34816                           // 34816  (reused as stage_T)
#define SM_STG   69632                           // 8 warps x 16 rows x 68 f = 34816
#define SM_META  104448
#define SM_SQB   (SM_META + 0)                   // float[128] sq of block bj
#define SM_TGB   (SM_META + 512)                 // int[128]   tgt of block bj
#define SM_TGI   (SM_META + 1024)                // int[128]   tgt of block bi
#define SM_SAP   (SM_META + 1536)                // uint[128]  rows (block bi)
#define SM_SAN   (SM_META + 2048)
#define SM_SAPC  (SM_META + 2560)                // uint[128]  cols (block bj)
#define SM_SANC  (SM_META + 3072)
#define SM_TOTAL (SM_META + 3584)                // 108032 -> 2 CTAs/SM

__device__ __forceinline__ uint32_t smem_u32(const void* p) {
    uint32_t a;
    asm("{ .reg .u64 t; cvta.to.shared.u64 t, %1; cvt.u32.u64 %0, t; }"
        : "=r"(a) : "l"(p));
    return a;
}

__device__ __forceinline__ void cp_async16(uint32_t dst, const void* src) {
    asm volatile("cp.async.cg.shared.global [%0], [%1], 16;"
                 :: "r"(dst), "l"(src) : "memory");
}

__device__ __forceinline__ void bulk_store(void* gdst, uint32_t ssrc, uint32_t bytes) {
    asm volatile("cp.async.bulk.global.shared::cta.bulk_group [%0], [%1], %2;"
                 :: "l"(gdst), "r"(ssrc), "r"(bytes) : "memory");
}

__device__ __forceinline__ void ldmatrix_x4(uint32_t* r, uint32_t addr) {
    asm volatile("ldmatrix.sync.aligned.m8n8.x4.shared.b16 {%0,%1,%2,%3}, [%4];"
                 : "=r"(r[0]), "=r"(r[1]), "=r"(r[2]), "=r"(r[3]) : "r"(addr));
}

__device__ __forceinline__ void mma16816(float* c, const uint32_t* a,
                                         uint32_t b0, uint32_t b1) {
    asm volatile(
        "mma.sync.aligned.m16n8k16.row.col.f32.bf16.bf16.f32 "
        "{%0,%1,%2,%3}, {%4,%5,%6,%7}, {%8,%9}, {%0,%1,%2,%3};"
        : "+f"(c[0]), "+f"(c[1]), "+f"(c[2]), "+f"(c[3])
        : "r"(a[0]), "r"(a[1]), "r"(a[2]), "r"(a[3]), "r"(b0), "r"(b1));
}

// ---------------------------------------------------------------------------
// Kernel 1: bf16-round X into g_xb4 + row sq-norms of ROUNDED values + init.
// ---------------------------------------------------------------------------
__global__ void prep_kernel(const float* __restrict__ x) {
    int row  = (blockIdx.x * blockDim.x + threadIdx.x) >> 5;
    int lane = threadIdx.x & 31;
    if (row >= N) return;
    const float4* xr = reinterpret_cast<const float4*>(x + (size_t)row * D);
    float4 v = xr[lane];
    union { __nv_bfloat162 h[2]; uint2 u; } ub;
    ub.h[0] = __floats2bfloat162_rn(v.x, v.y);
    ub.h[1] = __floats2bfloat162_rn(v.z, v.w);
    reinterpret_cast<uint2*>(g_xb4)[row * 32 + lane] = ub.u;
    float a0 = __bfloat162float(__float2bfloat16_rn(v.x));
    float a1 = __bfloat162float(__float2bfloat16_rn(v.y));
    float a2 = __bfloat162float(__float2bfloat16_rn(v.z));
    float a3 = __bfloat162float(__float2bfloat16_rn(v.w));
    float s = a0 * a0 + a1 * a1 + a2 * a2 + a3 * a3;
    #pragma unroll
    for (int o = 16; o > 0; o >>= 1) s += __shfl_xor_sync(0xffffffffu, s, o);
    if (lane == 0) {
        g_sq[row] = s;
        g_ap[row] = 0u;
        g_an[row] = 0x7f800000u;
    }
}

// ---------------------------------------------------------------------------
// Kernel 2: upper-triangular 128x128 tiles (2080 CTAs). Off-diagonal tiles
// mirrored via a full transposed tile staged in the retired A/B smem, then
// drained with 496B bulk DMAs (contiguous mirror rows).
// ---------------------------------------------------------------------------
__global__ __launch_bounds__(256, 2)
void dist_kernel(const int* __restrict__ tgt, float* __restrict__ out) {
    extern __shared__ char smem[];
    const uint32_t sbase = smem_u32(smem);
    const int t    = threadIdx.x;
    const int lane = t & 31;
    const int wid  = t >> 5;

    // decode upper-triangle tile (bi <= bj)
    int rem = blockIdx.x, bi = 0;
    while (rem >= NB - bi) { rem -= NB - bi; bi++; }
    const int bj = bi + rem;
    const int iBase = bi * TILE;
    const int jBase = bj * TILE;
    const bool isDiag = (bi == bj);

    float*    sqB  = (float*)(smem + SM_SQB);
    int*      tgB  = (int*)(smem + SM_TGB);
    int*      tgI  = (int*)(smem + SM_TGI);
    unsigned* sAp  = (unsigned*)(smem + SM_SAP);
    unsigned* sAn  = (unsigned*)(smem + SM_SAN);
    unsigned* sApC = (unsigned*)(smem + SM_SAPC);
    unsigned* sAnC = (unsigned*)(smem + SM_SANC);

    if (t < 128) {
        sqB[t]  = g_sq[jBase + t];
        tgB[t]  = tgt[jBase + t];
        tgI[t]  = tgt[iBase + t];
        sAp[t]  = 0u;          sAn[t]  = 0x7f800000u;
        sApC[t] = 0u;          sAnC[t] = 0x7f800000u;
    }

    // Tile fill via cp.async (pre-rounded bf16 rows)
    #pragma unroll
    for (int it = 0; it < 8; it++) {
        int idx = t + it * 256;               // 0..2047
        int row = idx >> 4, l = idx & 15;
        cp_async16(sbase + SM_A + row * PITCHB + l * 16,
                   &g_xb4[(size_t)(iBase + row) * 16 + l]);
        cp_async16(sbase + SM_B + row * PITCHB + l * 16,
                   &g_xb4[(size_t)(jBase + row) * 16 + l]);
    }
    asm volatile("cp.async.commit_group;" ::: "memory");
    asm volatile("cp.async.wait_group 0;" ::: "memory");
    __syncthreads();

    const int rw0 = (wid & 3) * 32;     // warp rows (tile-local)
    const int cw0 = (wid >> 2) * 64;    // warp cols (tile-local)
    const uint32_t aB = sbase + SM_A;
    const uint32_t bB = sbase + SM_B;
    const int lrow = lane & 15;
    const int koff = (lane >> 4) * 8;
    const int qr = lane >> 2;           // 0..7
    const int qc = 2 * (lane & 3);      // 0,2,4,6
    const float INF = __int_as_float(0x7f800000);

    float acc[2][8][4];
    #pragma unroll
    for (int mt = 0; mt < 2; mt++)
        #pragma unroll
        for (int nt = 0; nt < 8; nt++)
            #pragma unroll
            for (int e = 0; e < 4; e++) acc[mt][nt][e] = 0.f;

    #pragma unroll
    for (int ks = 0; ks < 8; ks++) {
        const int k0 = ks * 16;
        uint32_t af[2][4];
        #pragma unroll
        for (int mt = 0; mt < 2; mt++)
            ldmatrix_x4(af[mt],
                aB + (uint32_t)(rw0 + 16 * mt + lrow) * PITCHB + (k0 + koff) * 2);
        uint32_t bf[4][4];
        #pragma unroll
        for (int ng = 0; ng < 4; ng++)
            ldmatrix_x4(bf[ng],
                bB + (uint32_t)(cw0 + 16 * ng + lrow) * PITCHB + (k0 + koff) * 2);
        #pragma unroll
        for (int mt = 0; mt < 2; mt++)
            #pragma unroll
            for (int ng = 0; ng < 4; ng++) {
                mma16816(acc[mt][2 * ng + 0], af[mt], bf[ng][0], bf[ng][2]);
                mma16816(acc[mt][2 * ng + 1], af[mt], bf[ng][1], bf[ng][3]);
            }
    }
    __syncthreads();   // all ldmatrix reads done -> A/B region reusable (stage_T)

    float* stage   = (float*)(smem + SM_STG + wid * 4352);   // 16 rows x 68 f
    float* stage_T = (float*)(smem + SM_A);                  // 128 x TPITCH f

    #pragma unroll
    for (int mt = 0; mt < 2; mt++) {
        // ensure previous phase's bulk DMA has drained before restaging
        if (mt > 0 && lane < 16)
            asm volatile("cp.async.bulk.wait_group 0;" ::: "memory");
        __syncwarp();

        const int rl_lo = rw0 + 16 * mt + qr;
        const int rl_hi = rl_lo + 8;
        const int rg_lo = iBase + rl_lo;
        const int rg_hi = iBase + rl_hi;
        const float sq_lo = g_sq[rg_lo], sq_hi = g_sq[rg_hi];
        const int   tt_lo = tgI[rl_lo],  tt_hi = tgI[rl_hi];
        float ap_lo = 0.f, an_lo = INF, ap_hi = 0.f, an_hi = INF;

        #pragma unroll
        for (int nt = 0; nt < 8; nt++) {
            const int cl0 = cw0 + 8 * nt + qc;
            const float sc0 = sqB[cl0], sc1 = sqB[cl0 + 1];
            const int   tc0 = tgB[cl0], tc1 = tgB[cl0 + 1];
            const int   cg0 = jBase + cl0;

            float s00 = sq_lo + sc0 - 2.f * acc[mt][nt][0];
            float s01 = sq_lo + sc1 - 2.f * acc[mt][nt][1];
            float s10 = sq_hi + sc0 - 2.f * acc[mt][nt][2];
            float s11 = sq_hi + sc1 - 2.f * acc[mt][nt][3];
            float d00 = (s00 > 0.f) ? sqrtf(s00) : 0.f;
            float d01 = (s01 > 0.f) ? sqrtf(s01) : 0.f;
            float d10 = (s10 > 0.f) ? sqrtf(s10) : 0.f;
            float d11 = (s11 > 0.f) ? sqrtf(s11) : 0.f;
            if (rg_lo == cg0)     d00 = 0.f;      // exact diagonal, like ref
            if (rg_lo == cg0 + 1) d01 = 0.f;
            if (rg_hi == cg0)     d10 = 0.f;
            if (rg_hi == cg0 + 1) d11 = 0.f;

            if (tt_lo == tc0) ap_lo = fmaxf(ap_lo, d00); else an_lo = fminf(an_lo, d00);
            if (tt_lo == tc1) ap_lo = fmaxf(ap_lo, d01); else an_lo = fminf(an_lo, d01);
            if (tt_hi == tc0) ap_hi = fmaxf(ap_hi, d10); else an_hi = fminf(an_hi, d10);
            if (tt_hi == tc1) ap_hi = fmaxf(ap_hi, d11); else an_hi = fminf(an_hi, d11);

            const int sc = 8 * nt + qc + 1;       // +1 shift for bulk alignment
            stage[qr * 68 + sc]           = d00;
            stage[qr * 68 + sc + 1]       = d01;
            stage[(qr + 8) * 68 + sc]     = d10;
            stage[(qr + 8) * 68 + sc + 1] = d11;

            // transposed staging (conflict-free: 2*TPITCH = 8 mod 32)
            if (!isDiag) {
                stage_T[cl0 * TPITCH + rl_lo + 1]       = d00;
                stage_T[(cl0 + 1) * TPITCH + rl_lo + 1] = d01;
                stage_T[cl0 * TPITCH + rl_hi + 1]       = d10;
                stage_T[(cl0 + 1) * TPITCH + rl_hi + 1] = d11;
            }
        }

        // row-wise (block bi) reduction: quad shuffle + shared atomics
        #pragma unroll
        for (int o = 1; o <= 2; o <<= 1) {
            ap_lo = fmaxf(ap_lo, __shfl_xor_sync(0xffffffffu, ap_lo, o));
            an_lo = fminf(an_lo, __shfl_xor_sync(0xffffffffu, an_lo, o));
            ap_hi = fmaxf(ap_hi, __shfl_xor_sync(0xffffffffu, ap_hi, o));
            an_hi = fminf(an_hi, __shfl_xor_sync(0xffffffffu, an_hi, o));
        }
        if ((lane & 3) == 0) {
            atomicMax(&sAp[rl_lo], __float_as_uint(ap_lo));
            atomicMin(&sAn[rl_lo], __float_as_uint(an_lo));
            atomicMax(&sAp[rl_hi], __float_as_uint(ap_hi));
            atomicMin(&sAn[rl_hi], __float_as_uint(an_hi));
        }
        __syncwarp();
        asm volatile("fence.proxy.async.shared::cta;" ::: "memory");

        // normal-orientation bulk store (cols 3..62 of slab) + scalar edges
        const size_t rowBase = (size_t)(iBase + rw0 + 16 * mt) * N + jBase + cw0;
        if (lane < 16) {
            bulk_store(out + rowBase + (size_t)lane * N + 3,
                       sbase + SM_STG + wid * 4352u + (uint32_t)lane * 272u + 16u,
                       240u);
            asm volatile("cp.async.bulk.commit_group;" ::: "memory");
        }
        #pragma unroll
        for (int it = 0; it < 2; it++) {
            int idx = it * 32 + lane;
            int row = idx >> 2, e = idx & 3;
            int jl  = (e == 3) ? 63 : e;
            out[rowBase + (size_t)row * N + jl] = stage[row * 68 + jl + 1];
        }

        // col-wise (block bj) reduction from the normal staged tile
        if (!isDiag) {
            const int c0 = cw0 + 2 * lane;            // 2 cols per lane
            const int tc0 = tgB[c0], tc1 = tgB[c0 + 1];
            float apc0 = 0.f, anc0 = INF, apc1 = 0.f, anc1 = INF;
            #pragma unroll
            for (int r = 0; r < 16; r++) {
                const int rt = tgI[rw0 + 16 * mt + r];
                float v0 = stage[r * 68 + 2 * lane + 1];
                float v1 = stage[r * 68 + 2 * lane + 2];
                if (rt == tc0) apc0 = fmaxf(apc0, v0); else anc0 = fminf(anc0, v0);
                if (rt == tc1) apc1 = fmaxf(apc1, v1); else anc1 = fminf(anc1, v1);
            }
            atomicMax(&sApC[c0],     __float_as_uint(apc0));
            atomicMin(&sAnC[c0],     __float_as_uint(anc0));
            atomicMax(&sApC[c0 + 1], __float_as_uint(apc1));
            atomicMin(&sAnC[c0 + 1], __float_as_uint(anc1));
        }
    }

    __syncthreads();   // stage_T fully assembled across all warps/phases

    // Mirror drain: 128 contiguous out-rows, one 496B bulk DMA each
    // (cols iBase+3..iBase+126 are 16B-aligned under the d_out+1 shift),
    // plus 4 edge scalars per row.
    if (!isDiag) {
        asm volatile("fence.proxy.async.shared::cta;" ::: "memory");
        if (t < 128) {
            bulk_store(out + (size_t)(jBase + t) * N + iBase + 3,
                       sbase + SM_A + (uint32_t)t * (TPITCH * 4) + 16u, 496u);
            asm volatile("cp.async.bulk.commit_group;" ::: "memory");
        }
        #pragma unroll
        for (int it = 0; it < 2; it++) {
            int idx = it * 256 + t;               // 0..511
            int row = idx >> 2, e = idx & 3;
            int jl  = (e == 3) ? 127 : e;
            out[(size_t)(jBase + row) * N + iBase + jl] = stage_T[row * TPITCH + jl + 1];
        }
    }

    __syncthreads();
    if (t < 128) {
        atomicMax(&g_ap[iBase + t], sAp[t]);
        atomicMin(&g_an[iBase + t], sAn[t]);
        if (!isDiag) {
            atomicMax(&g_ap[jBase + t], sApC[t]);
            atomicMin(&g_an[jBase + t], sAnC[t]);
        }
    }
    // drain all bulk DMAs before smem is recycled by the next CTA
    asm volatile("cp.async.bulk.wait_group 0;" ::: "memory");
}

// ---------------------------------------------------------------------------
// Kernel 3: loss = mean(relu(ap - an + margin)). Single block.
// ---------------------------------------------------------------------------
__global__ void loss_kernel(float* __restrict__ out) {
    __shared__ float red[32];
    float s = 0.f;
    for (int i = threadIdx.x; i < N; i += blockDim.x) {
        float ap = __uint_as_float(g_ap[i]);
        float an = __uint_as_float(g_an[i]);
        float v  = ap - an + MARGIN;
        s += (v > 0.f) ? v : 0.f;
    }
    #pragma unroll
    for (int o = 16; o > 0; o >>= 1) s += __shfl_xor_sync(0xffffffffu, s, o);
    int lane = threadIdx.x & 31, wid = threadIdx.x >> 5;
    if (lane == 0) red[wid] = s;
    __syncthreads();
    if (wid == 0) {
        s = (lane < (blockDim.x >> 5)) ? red[lane] : 0.f;
        #pragma unroll
        for (int o = 16; o > 0; o >>= 1) s += __shfl_xor_sync(0xffffffffu, s, o);
        if (lane == 0) out[0] = s / (float)N;
    }
}

// ---------------------------------------------------------------------------
extern "C" void kernel_launch(void* const* d_in, const int* in_sizes, int n_in,
                              void* d_out, int out_size) {
    const float* x   = (const float*)d_in[0];
    const int*   tgt = (const int*)d_in[1];
    float* out = (float*)d_out;           // out[0] = loss, out[1..] = dist

    cudaFuncSetAttribute(dist_kernel,
                         cudaFuncAttributeMaxDynamicSharedMemorySize, SM_TOTAL);

    prep_kernel<<<N / 8, 256>>>(x);

    dist_kernel<<<NB * (NB + 1) / 2, 256, SM_TOTAL>>>(tgt, out + 1);

    loss_kernel<<<1, 1024>>>(out);
}